// round 7
// baseline (speedup 1.0000x reference)
#include <cuda_runtime.h>
#include <cstdint>
#include <cstddef>

#define Bsz  64
#define Hd   512
#define Tlen 512
#define G4H  2048
#define Ed   256
#define NCTA 128
#define NTHR 512
#define HB   (Hd * Bsz)
#define PPAD 18

typedef unsigned long long ull;

// ---------------- device scratch (static, allowed) ----------------
__device__ __align__(256) float g_xg[(size_t)Tlen * G4H * Bsz];  // 256 MB
__device__ __align__(256) float g_h0[2 * HB];
__device__ __align__(256) float g_h1[2 * HB];
__device__ unsigned g_cnt = 0;
__device__ unsigned g_gen = 0;

// ---------------- packed f32x2 helpers ----------------
__device__ __forceinline__ ull pk2f(float x) {
    ull r; asm("mov.b64 %0, {%1, %1};" : "=l"(r) : "f"(x)); return r;
}
__device__ __forceinline__ void ffma2(ull& a, ull h, ull w) {
    asm("fma.rn.f32x2 %0, %1, %2, %0;" : "+l"(a) : "l"(h), "l"(w));
}
__device__ __forceinline__ void up2(ull v, float& x, float& y) {
    unsigned lo, hi;
    asm("mov.b64 {%0, %1}, %2;" : "=r"(lo), "=r"(hi) : "l"(v));
    x = __uint_as_float(lo); y = __uint_as_float(hi);
}
__device__ __forceinline__ float sigm(float x) { return 1.f / (1.f + __expf(-x)); }

// ---------------- grid-wide barrier (128 co-resident CTAs) ----------------
__device__ __forceinline__ void gridbar() {
    __threadfence();
    __syncthreads();
    if (threadIdx.x == 0) {
        volatile unsigned* vg = &g_gen;
        unsigned gen = *vg;
        if (atomicAdd(&g_cnt, 1u) == NCTA - 1u) {
            atomicExch(&g_cnt, 0u);
            __threadfence();
            atomicAdd(&g_gen, 1u);
        } else {
            while (*vg == gen) { }
        }
        __threadfence();
    }
    __syncthreads();
}

// =================================================================
// Kernel A: Xg[t][row][b] = b0[row] + sum_e emb[x[b,t],e] * Wih0[row,e]
// =================================================================
__global__ void __launch_bounds__(256) kA(const int* __restrict__ x,
                                          const float* __restrict__ emb,
                                          const float* __restrict__ Wih0,
                                          const float* __restrict__ b0) {
    __shared__ float ws[64 * 33];      // [row][e]
    __shared__ float xs2[32 * 66];     // [e][b] transposed, padded
    __shared__ int   xr[64];
    const int tid = threadIdx.x;
    const int t   = blockIdx.x;
    const int rb  = blockIdx.y * 64;
    if (tid < 64) xr[tid] = x[tid * Tlen + t];
    __syncthreads();

    ull accA[4], accB[4];
#pragma unroll
    for (int j = 0; j < 4; j++) { accA[j] = 0ull; accB[j] = 0ull; }
    const int r4 = tid >> 4;
    const int q4 = (tid & 15) * 4;

    for (int ec = 0; ec < Ed; ec += 32) {
#pragma unroll
        for (int i = 0; i < 8; i++) {
            int idx = tid + i * 256;
            int a = idx >> 5, e = idx & 31;
            ws[a * 33 + e] = Wih0[(rb + a) * Ed + ec + e];
            xs2[e * 66 + a] = emb[(size_t)xr[a] * Ed + ec + e];
        }
        __syncthreads();
#pragma unroll 8
        for (int e = 0; e < 32; e++) {
            ull x01 = *(const ull*)&xs2[e * 66 + q4];
            ull x23 = *(const ull*)&xs2[e * 66 + q4 + 2];
#pragma unroll
            for (int j = 0; j < 4; j++) {
                ull w2 = pk2f(ws[(r4 * 4 + j) * 33 + e]);
                ffma2(accA[j], x01, w2);
                ffma2(accB[j], x23, w2);
            }
        }
        __syncthreads();
    }
#pragma unroll
    for (int j = 0; j < 4; j++) {
        int row = rb + r4 * 4 + j;
        float bv = b0[row];
        float4 o;
        up2(accA[j], o.x, o.y);
        up2(accB[j], o.z, o.w);
        o.x += bv; o.y += bv; o.z += bv; o.w += bv;
        *(float4*)(g_xg + ((size_t)t * G4H + row) * Bsz + q4) = o;
    }
}

// =================================================================
__global__ void kzero() {
    int i = blockIdx.x * 256 + threadIdx.x;   // grid 256 -> 65536 = 2*HB
    g_h0[i] = 0.f;
    g_h1[i] = 0.f;
}

// =================================================================
// Persistent recurrent kernel: 128 CTAs x 512 threads (16 warps).
// CTA owns 4 units (16 gate rows/layer). 16 warps split k; each thread
// computes 8 rows (as 4 f32x2 row-pairs) x 4 batches over its slice.
// h via __ldcg float4, depth-8 prefetch ring (unroll 8 -> static idx).
// smem: wT0[512][16] | wT1[1024][16] | pbuf[16][64][18]  = 168KB
// =================================================================
#define SM_WT0  0
#define SM_WT1  8192
#define SM_PBUF 24576
#define SM_TOTF (24576 + 16 * 64 * PPAD)
#define SMEMB   (SM_TOTF * 4)

template <int NK>
__device__ __forceinline__ void gemm2(ull (&acc)[4][4], const float* wT, int kw0,
                                      const float* __restrict__ hsrc, int kh0,
                                      int rh, int q) {
    const float4* hp = (const float4*)hsrc + q;   // 16 float4 per k-row
    float4 hbuf[8];
#pragma unroll
    for (int j = 0; j < 8; j++) hbuf[j] = __ldcg(hp + (size_t)(kh0 + j) * 16);
#pragma unroll 8
    for (int i = 0; i < NK; i++) {
        float4 hc = hbuf[i & 7];
        if (i + 8 < NK) hbuf[i & 7] = __ldcg(hp + (size_t)(kh0 + i + 8) * 16);
        const ulonglong2* wp = (const ulonglong2*)(wT + (kw0 + i) * 16 + rh * 8);
        ulonglong2 wa = wp[0];
        ulonglong2 wb = wp[1];
        ull h2;
        h2 = pk2f(hc.x);
        ffma2(acc[0][0], wa.x, h2); ffma2(acc[1][0], wa.y, h2);
        ffma2(acc[2][0], wb.x, h2); ffma2(acc[3][0], wb.y, h2);
        h2 = pk2f(hc.y);
        ffma2(acc[0][1], wa.x, h2); ffma2(acc[1][1], wa.y, h2);
        ffma2(acc[2][1], wb.x, h2); ffma2(acc[3][1], wb.y, h2);
        h2 = pk2f(hc.z);
        ffma2(acc[0][2], wa.x, h2); ffma2(acc[1][2], wa.y, h2);
        ffma2(acc[2][2], wb.x, h2); ffma2(acc[3][2], wb.y, h2);
        h2 = pk2f(hc.w);
        ffma2(acc[0][3], wa.x, h2); ffma2(acc[1][3], wa.y, h2);
        ffma2(acc[2][3], wb.x, h2); ffma2(acc[3][3], wb.y, h2);
    }
}

__device__ __forceinline__ void storep(float* pbuf, ull (&acc)[4][4],
                                       int w, int rh, int q) {
#pragma unroll
    for (int p = 0; p < 4; p++)
#pragma unroll
        for (int j = 0; j < 4; j++)
            *(ull*)&pbuf[(w * 64 + q * 4 + j) * PPAD + rh * 8 + 2 * p] = acc[p][j];
}

__global__ void __launch_bounds__(NTHR, 1) lstm_rec(const float* __restrict__ Whh0,
                                                    const float* __restrict__ Wih1,
                                                    const float* __restrict__ Whh1,
                                                    const float* __restrict__ b1) {
    extern __shared__ float sm[];
    float* wT0  = sm + SM_WT0;
    float* wT1  = sm + SM_WT1;
    float* pbuf = sm + SM_PBUF;

    const int tid = threadIdx.x;
    const int u0  = blockIdx.x * 4;

    // ---- stage weights once, transposed: wT[k][j], j = unit*4 + gate ----
    for (int idx = tid; idx < 512 * 16; idx += NTHR) {
        int j = idx >> 9, k = idx & 511;
        int row = ((j & 3) << 9) + u0 + (j >> 2);
        wT0[k * 16 + j] = Whh0[row * Hd + k];
    }
    for (int idx = tid; idx < 1024 * 16; idx += NTHR) {
        int j = idx >> 10, k = idx & 1023;
        int row = ((j & 3) << 9) + u0 + (j >> 2);
        wT1[k * 16 + j] = (k < 512) ? Wih1[row * Hd + k] : Whh1[row * Hd + (k - 512)];
    }
    __syncthreads();

    // gemm role
    const int w    = tid >> 5;        // warp 0..15 = k-slice
    const int lane = tid & 31;
    const int rh   = lane >> 4;       // row octet
    const int q    = lane & 15;       // batch quad
    // update role (tid < 256)
    const int uu = tid >> 6;
    const int bb = tid & 63;
    float c0 = 0.f, c1 = 0.f;
    float b1v[4] = {0.f, 0.f, 0.f, 0.f};
    if (tid < 256)
#pragma unroll
        for (int g = 0; g < 4; g++) b1v[g] = b1[(g << 9) + u0 + uu];

    for (int t = 0; t < Tlen; t++) {
        const int p = t & 1;

        float xgv[4] = {0.f, 0.f, 0.f, 0.f};
        if (tid < 256)
#pragma unroll
            for (int g = 0; g < 4; g++)
                xgv[g] = __ldcs(&g_xg[((size_t)t * G4H + (g << 9) + u0 + uu) * Bsz + bb]);

        // ========== phase 1: partial gates0 = Whh0[:, slice] @ h0_prev ==========
        {
            ull acc[4][4];
#pragma unroll
            for (int a = 0; a < 4; a++)
#pragma unroll
                for (int b = 0; b < 4; b++) acc[a][b] = 0ull;
            gemm2<32>(acc, wT0, w * 32, g_h0 + (p ^ 1) * HB, w * 32, rh, q);
            storep(pbuf, acc, w, rh, q);
        }
        __syncthreads();
        if (tid < 256) {
            float s[4] = {xgv[0], xgv[1], xgv[2], xgv[3]};
#pragma unroll
            for (int w16 = 0; w16 < 16; w16++) {
                const float* pp = &pbuf[(w16 * 64 + bb) * PPAD + uu * 4];
                float2 v0 = *(const float2*)pp;
                float2 v1 = *(const float2*)(pp + 2);
                s[0] += v0.x; s[1] += v0.y; s[2] += v1.x; s[3] += v1.y;
            }
            c0 = sigm(s[1]) * c0 + sigm(s[0]) * tanhf(s[2]);
            float h0n = sigm(s[3]) * tanhf(c0);
            g_h0[p * HB + (u0 + uu) * 64 + bb] = h0n;
        }

        gridbar();    // publish h0n to all CTAs; fences pbuf reuse

        // ========== phase 2: partial gates1 = [Wih1|Whh1][:, slice] @ [h0n; h1_prev] ==========
        {
            ull acc[4][4];
#pragma unroll
            for (int a = 0; a < 4; a++)
#pragma unroll
                for (int b = 0; b < 4; b++) acc[a][b] = 0ull;
            if (w < 8)
                gemm2<64>(acc, wT1, w * 64, g_h0 + p * HB, w * 64, rh, q);
            else
                gemm2<64>(acc, wT1, w * 64, g_h1 + (p ^ 1) * HB, (w - 8) * 64, rh, q);
            storep(pbuf, acc, w, rh, q);
        }
        __syncthreads();
        if (tid < 256) {
            float s[4] = {b1v[0], b1v[1], b1v[2], b1v[3]};
#pragma unroll
            for (int w16 = 0; w16 < 16; w16++) {
                const float* pp = &pbuf[(w16 * 64 + bb) * PPAD + uu * 4];
                float2 v0 = *(const float2*)pp;
                float2 v1 = *(const float2*)(pp + 2);
                s[0] += v0.x; s[1] += v0.y; s[2] += v1.x; s[3] += v1.y;
            }
            c1 = sigm(s[1]) * c1 + sigm(s[0]) * tanhf(s[2]);
            float h1n = sigm(s[3]) * tanhf(c1);
            g_h1[p * HB + (u0 + uu) * 64 + bb] = h1n;
        }
        __syncthreads();   // pbuf reads done before next step's stores
    }
}

// =================================================================
// classifier: 1024 threads, k split 8 ways + smem tree
// =================================================================
__global__ void __launch_bounds__(1024) kclf(const float* __restrict__ Wclf,
                                             const float* __restrict__ bclf,
                                             float* __restrict__ out) {
    __shared__ float red[1024];
    const int t  = threadIdx.x;
    const int o  = t & 1;
    const int b  = (t >> 1) & 63;
    const int ks = t >> 7;
    const float* h = g_h1 + HB;       // parity of t=511 is 1
    float s = 0.f;
#pragma unroll 8
    for (int i = 0; i < 64; i++) {
        int k = ks * 64 + i;
        s = fmaf(Wclf[o * Hd + k], h[k * 64 + b], s);
    }
    red[t] = s;
    __syncthreads();
    if (ks == 0) {
        float v = s + bclf[o];
#pragma unroll
        for (int w8 = 1; w8 < 8; w8++) v += red[t + w8 * 128];
        out[b * 2 + o] = v;
    }
}

// =================================================================
extern "C" void kernel_launch(void* const* d_in, const int* in_sizes, int n_in,
                              void* d_out, int out_size) {
    const int*   x    = (const int*)  d_in[0];
    const float* emb  = (const float*)d_in[1];
    const float* Wih0 = (const float*)d_in[2];
    const float* Whh0 = (const float*)d_in[3];
    const float* b0   = (const float*)d_in[4];
    const float* Wih1 = (const float*)d_in[5];
    const float* Whh1 = (const float*)d_in[6];
    const float* b1   = (const float*)d_in[7];
    const float* Wclf = (const float*)d_in[8];
    const float* bclf = (const float*)d_in[9];
    float* out = (float*)d_out;

    cudaFuncSetAttribute(lstm_rec, cudaFuncAttributeMaxDynamicSharedMemorySize, SMEMB);

    kzero<<<256, 256>>>();
    dim3 gA(Tlen, 32);
    kA<<<gA, 256>>>(x, emb, Wih0, b0);
    lstm_rec<<<NCTA, NTHR, SMEMB>>>(Whh0, Wih1, Whh1, b1);
    kclf<<<1, 1024>>>(Wclf, bclf, out);
}

// round 8
// speedup vs baseline: 1.0881x; 1.0881x over previous
#include <cuda_runtime.h>
#include <cstdint>
#include <cstddef>

#define Bsz  64
#define Hd   512
#define Tlen 512
#define G4H  2048
#define Ed   256
#define NCTA 128
#define NTHR 512
#define HB   (Hd * Bsz)
#define PPAD 18

typedef unsigned long long ull;

// ---------------- device scratch (static, allowed) ----------------
__device__ __align__(256) float g_xg[(size_t)Tlen * G4H * Bsz];  // 256 MB
__device__ __align__(256) float g_h0[2 * HB];
__device__ __align__(256) float g_h1[2 * HB];
__device__ unsigned g_bar1;   // monotonic arrive counters (reset by kzero each launch)
__device__ unsigned g_bar2;

// ---------------- packed f32x2 helpers ----------------
__device__ __forceinline__ ull pk2f(float x) {
    ull r; asm("mov.b64 %0, {%1, %1};" : "=l"(r) : "f"(x)); return r;
}
__device__ __forceinline__ void ffma2(ull& a, ull h, ull w) {
    asm("fma.rn.f32x2 %0, %1, %2, %0;" : "+l"(a) : "l"(h), "l"(w));
}
__device__ __forceinline__ void up2(ull v, float& x, float& y) {
    unsigned lo, hi;
    asm("mov.b64 {%0, %1}, %2;" : "=r"(lo), "=r"(hi) : "l"(v));
    x = __uint_as_float(lo); y = __uint_as_float(hi);
}
__device__ __forceinline__ float sigm(float x) {
    return __fdividef(1.f, 1.f + __expf(-x));
}
__device__ __forceinline__ float tanh_fast(float x) {
    float e = __expf(2.f * x);
    return 1.f - __fdividef(2.f, e + 1.f);   // saturates to +/-1, NaN-free
}

// ---------------- split grid barrier: monotonic release/acquire ----------------
// arrive: caller guarantees a preceding __syncthreads covering the stores.
__device__ __forceinline__ void bar_arrive(unsigned* ctr) {
    if (threadIdx.x == 0)
        asm volatile("red.release.gpu.global.add.u32 [%0], 1;" :: "l"(ctr) : "memory");
}
__device__ __forceinline__ void bar_wait(unsigned* ctr, unsigned target) {
    if (threadIdx.x == 0) {
        unsigned v;
        do {
            asm volatile("ld.acquire.gpu.global.u32 %0, [%1];" : "=r"(v) : "l"(ctr) : "memory");
        } while (v < target);
    }
    __syncthreads();
}

// =================================================================
// Kernel A: Xg[t][row][b] = b0[row] + sum_e emb[x[b,t],e] * Wih0[row,e]
// =================================================================
__global__ void __launch_bounds__(256) kA(const int* __restrict__ x,
                                          const float* __restrict__ emb,
                                          const float* __restrict__ Wih0,
                                          const float* __restrict__ b0) {
    __shared__ float ws[64 * 33];      // [row][e]
    __shared__ float xs2[32 * 66];     // [e][b] transposed, padded
    __shared__ int   xr[64];
    const int tid = threadIdx.x;
    const int t   = blockIdx.x;
    const int rb  = blockIdx.y * 64;
    if (tid < 64) xr[tid] = x[tid * Tlen + t];
    __syncthreads();

    ull accA[4], accB[4];
#pragma unroll
    for (int j = 0; j < 4; j++) { accA[j] = 0ull; accB[j] = 0ull; }
    const int r4 = tid >> 4;
    const int q4 = (tid & 15) * 4;

    for (int ec = 0; ec < Ed; ec += 32) {
#pragma unroll
        for (int i = 0; i < 8; i++) {
            int idx = tid + i * 256;
            int a = idx >> 5, e = idx & 31;
            ws[a * 33 + e] = Wih0[(rb + a) * Ed + ec + e];
            xs2[e * 66 + a] = emb[(size_t)xr[a] * Ed + ec + e];
        }
        __syncthreads();
#pragma unroll 8
        for (int e = 0; e < 32; e++) {
            ull x01 = *(const ull*)&xs2[e * 66 + q4];
            ull x23 = *(const ull*)&xs2[e * 66 + q4 + 2];
#pragma unroll
            for (int j = 0; j < 4; j++) {
                ull w2 = pk2f(ws[(r4 * 4 + j) * 33 + e]);
                ffma2(accA[j], x01, w2);
                ffma2(accB[j], x23, w2);
            }
        }
        __syncthreads();
    }
#pragma unroll
    for (int j = 0; j < 4; j++) {
        int row = rb + r4 * 4 + j;
        float bv = b0[row];
        float4 o;
        up2(accA[j], o.x, o.y);
        up2(accB[j], o.z, o.w);
        o.x += bv; o.y += bv; o.z += bv; o.w += bv;
        *(float4*)(g_xg + ((size_t)t * G4H + row) * Bsz + q4) = o;
    }
}

// =================================================================
__global__ void kzero() {
    int i = blockIdx.x * 256 + threadIdx.x;   // grid 256 -> 65536 = 2*HB
    g_h0[i] = 0.f;
    g_h1[i] = 0.f;
    if (i == 0) { g_bar1 = 0u; g_bar2 = 0u; }  // reset across graph replays
}

// =================================================================
// Persistent recurrent kernel: 128 CTAs x 512 threads (16 warps).
// CTA owns 4 units (16 gate rows/layer). 16 warps split k; each thread
// computes 8 rows (4 f32x2 row-pairs) x 4 batches over its slice.
// h via __ldcg float4, depth-8 prefetch ring (unroll 8 -> static idx).
// Split-barrier schedule hides both grid syncs behind GEMM regions.
// smem: wT0[512][16] | wT1[1024][16] | pbuf[16][64][18]  = 168KB
// =================================================================
#define SM_WT0  0
#define SM_WT1  8192
#define SM_PBUF 24576
#define SM_TOTF (24576 + 16 * 64 * PPAD)
#define SMEMB   (SM_TOTF * 4)

template <int NK>
__device__ __forceinline__ void gemm2(ull (&acc)[4][4], const float* wT, int kw0,
                                      const float* __restrict__ hsrc, int kh0,
                                      int rh, int q) {
    const float4* hp = (const float4*)hsrc + q;   // 16 float4 per k-row
    float4 hbuf[8];
#pragma unroll
    for (int j = 0; j < 8; j++) hbuf[j] = __ldcg(hp + (size_t)(kh0 + j) * 16);
#pragma unroll 8
    for (int i = 0; i < NK; i++) {
        float4 hc = hbuf[i & 7];
        if (i + 8 < NK) hbuf[i & 7] = __ldcg(hp + (size_t)(kh0 + i + 8) * 16);
        const ulonglong2* wp = (const ulonglong2*)(wT + (kw0 + i) * 16 + rh * 8);
        ulonglong2 wa = wp[0];
        ulonglong2 wb = wp[1];
        ull h2;
        h2 = pk2f(hc.x);
        ffma2(acc[0][0], wa.x, h2); ffma2(acc[1][0], wa.y, h2);
        ffma2(acc[2][0], wb.x, h2); ffma2(acc[3][0], wb.y, h2);
        h2 = pk2f(hc.y);
        ffma2(acc[0][1], wa.x, h2); ffma2(acc[1][1], wa.y, h2);
        ffma2(acc[2][1], wb.x, h2); ffma2(acc[3][1], wb.y, h2);
        h2 = pk2f(hc.z);
        ffma2(acc[0][2], wa.x, h2); ffma2(acc[1][2], wa.y, h2);
        ffma2(acc[2][2], wb.x, h2); ffma2(acc[3][2], wb.y, h2);
        h2 = pk2f(hc.w);
        ffma2(acc[0][3], wa.x, h2); ffma2(acc[1][3], wa.y, h2);
        ffma2(acc[2][3], wb.x, h2); ffma2(acc[3][3], wb.y, h2);
    }
}

__device__ __forceinline__ void storep(float* pbuf, ull (&acc)[4][4],
                                       int w, int rh, int q) {
#pragma unroll
    for (int p = 0; p < 4; p++)
#pragma unroll
        for (int j = 0; j < 4; j++)
            *(ull*)&pbuf[(w * 64 + q * 4 + j) * PPAD + rh * 8 + 2 * p] = acc[p][j];
}

__global__ void __launch_bounds__(NTHR, 1) lstm_rec(const float* __restrict__ Whh0,
                                                    const float* __restrict__ Wih1,
                                                    const float* __restrict__ Whh1,
                                                    const float* __restrict__ b1) {
    extern __shared__ float sm[];
    float* wT0  = sm + SM_WT0;
    float* wT1  = sm + SM_WT1;
    float* pbuf = sm + SM_PBUF;

    const int tid = threadIdx.x;
    const int u0  = blockIdx.x * 4;

    // ---- stage weights once, transposed: wT[k][j], j = unit*4 + gate ----
    for (int idx = tid; idx < 512 * 16; idx += NTHR) {
        int j = idx >> 9, k = idx & 511;
        int row = ((j & 3) << 9) + u0 + (j >> 2);
        wT0[k * 16 + j] = Whh0[row * Hd + k];
    }
    for (int idx = tid; idx < 1024 * 16; idx += NTHR) {
        int j = idx >> 10, k = idx & 1023;
        int row = ((j & 3) << 9) + u0 + (j >> 2);
        wT1[k * 16 + j] = (k < 512) ? Wih1[row * Hd + k] : Whh1[row * Hd + (k - 512)];
    }
    __syncthreads();

    // gemm role
    const int w    = tid >> 5;        // warp 0..15 = k-slice
    const int lane = tid & 31;
    const int rh   = lane >> 4;       // row octet
    const int q    = lane & 15;       // batch quad
    // update role (tid < 256)
    const int uu = tid >> 6;
    const int bb = tid & 63;
    float c0 = 0.f, c1 = 0.f;
    float b1v[4] = {0.f, 0.f, 0.f, 0.f};
    if (tid < 256)
#pragma unroll
        for (int g = 0; g < 4; g++) b1v[g] = b1[(g << 9) + u0 + uu];

    for (int t = 0; t < Tlen; t++) {
        const int p = t & 1;

        float xgv[4] = {0.f, 0.f, 0.f, 0.f};
        if (tid < 256)
#pragma unroll
            for (int g = 0; g < 4; g++)
                xgv[g] = __ldcs(&g_xg[((size_t)t * G4H + (g << 9) + u0 + uu) * Bsz + bb]);

        // ========== phase 1: partial gates0 = Whh0[:, slice] @ h0_prev ==========
        {
            ull acc[4][4];
#pragma unroll
            for (int a = 0; a < 4; a++)
#pragma unroll
                for (int b = 0; b < 4; b++) acc[a][b] = 0ull;
            gemm2<32>(acc, wT0, w * 32, g_h0 + (p ^ 1) * HB, w * 32, rh, q);
            storep(pbuf, acc, w, rh, q);
        }
        __syncthreads();
        if (tid < 256) {
            float s[4] = {xgv[0], xgv[1], xgv[2], xgv[3]};
#pragma unroll
            for (int w16 = 0; w16 < 16; w16++) {
                const float* pp = &pbuf[(w16 * 64 + bb) * PPAD + uu * 4];
                float2 v0 = *(const float2*)pp;
                float2 v1 = *(const float2*)(pp + 2);
                s[0] += v0.x; s[1] += v0.y; s[2] += v1.x; s[3] += v1.y;
            }
            c0 = sigm(s[1]) * c0 + sigm(s[0]) * tanh_fast(s[2]);
            float h0n = sigm(s[3]) * tanh_fast(c0);
            g_h0[p * HB + (u0 + uu) * 64 + bb] = h0n;
        }
        __syncthreads();               // h0n stores + pbuf reads complete
        bar_arrive(&g_bar1);           // publish h0n (release)

        // ========== phase 2B: acc2 = Whh1[:, slice] @ h1_prev (pre-bar work) ==========
        ull acc2[4][4];
#pragma unroll
        for (int a = 0; a < 4; a++)
#pragma unroll
            for (int b = 0; b < 4; b++) acc2[a][b] = 0ull;

        bar_wait(&g_bar2, NCTA * (unsigned)t);     // h1_prev visible (no-op at t=0; hidden otherwise)
        gemm2<32>(acc2, wT1, 512 + w * 32, g_h1 + (p ^ 1) * HB, w * 32, rh, q);

        // ========== wait bar1 (hidden behind phase 2B), then phase 2A over h0n ==========
        bar_wait(&g_bar1, NCTA * (unsigned)(t + 1));
        gemm2<32>(acc2, wT1, w * 32, g_h0 + p * HB, w * 32, rh, q);
        storep(pbuf, acc2, w, rh, q);

        __syncthreads();
        if (tid < 256) {
            float s[4] = {b1v[0], b1v[1], b1v[2], b1v[3]};
#pragma unroll
            for (int w16 = 0; w16 < 16; w16++) {
                const float* pp = &pbuf[(w16 * 64 + bb) * PPAD + uu * 4];
                float2 v0 = *(const float2*)pp;
                float2 v1 = *(const float2*)(pp + 2);
                s[0] += v0.x; s[1] += v0.y; s[2] += v1.x; s[3] += v1.y;
            }
            c1 = sigm(s[1]) * c1 + sigm(s[0]) * tanh_fast(s[2]);
            float h1n = sigm(s[3]) * tanh_fast(c1);
            g_h1[p * HB + (u0 + uu) * 64 + bb] = h1n;
        }
        __syncthreads();               // h1n stores + pbuf reads complete
        bar_arrive(&g_bar2);           // publish h1n (release); next step waits when needed
    }
}

// =================================================================
// classifier: 1024 threads, k split 8 ways + smem tree
// =================================================================
__global__ void __launch_bounds__(1024) kclf(const float* __restrict__ Wclf,
                                             const float* __restrict__ bclf,
                                             float* __restrict__ out) {
    __shared__ float red[1024];
    const int t  = threadIdx.x;
    const int o  = t & 1;
    const int b  = (t >> 1) & 63;
    const int ks = t >> 7;
    const float* h = g_h1 + HB;       // parity of t=511 is 1
    float s = 0.f;
#pragma unroll 8
    for (int i = 0; i < 64; i++) {
        int k = ks * 64 + i;
        s = fmaf(Wclf[o * Hd + k], h[k * 64 + b], s);
    }
    red[t] = s;
    __syncthreads();
    if (ks == 0) {
        float v = s + bclf[o];
#pragma unroll
        for (int w8 = 1; w8 < 8; w8++) v += red[t + w8 * 128];
        out[b * 2 + o] = v;
    }
}

// =================================================================
extern "C" void kernel_launch(void* const* d_in, const int* in_sizes, int n_in,
                              void* d_out, int out_size) {
    const int*   x    = (const int*)  d_in[0];
    const float* emb  = (const float*)d_in[1];
    const float* Wih0 = (const float*)d_in[2];
    const float* Whh0 = (const float*)d_in[3];
    const float* b0   = (const float*)d_in[4];
    const float* Wih1 = (const float*)d_in[5];
    const float* Whh1 = (const float*)d_in[6];
    const float* b1   = (const float*)d_in[7];
    const float* Wclf = (const float*)d_in[8];
    const float* bclf = (const float*)d_in[9];
    float* out = (float*)d_out;

    cudaFuncSetAttribute(lstm_rec, cudaFuncAttributeMaxDynamicSharedMemorySize, SMEMB);

    kzero<<<256, 256>>>();
    dim3 gA(Tlen, 32);
    kA<<<gA, 256>>>(x, emb, Wih0, b0);
    lstm_rec<<<NCTA, NTHR, SMEMB>>>(Whh0, Wih1, Whh1, b1);
    kclf<<<1, 1024>>>(Wclf, bclf, out);
}